// round 2
// baseline (speedup 1.0000x reference)
#include <cuda_runtime.h>

// Problem constants
constexpr int Bc  = 4;
constexpr int Sc  = 2048;
constexpr int Dc  = 1024;
constexpr int Hc  = 16;
constexpr int HDc = 64;
constexpr int TD3 = 3 * Dc;          // 3072
constexpr int Mrows = Bc * Sc;       // 8192

// Scratch (device globals; no allocation in kernel_launch)
__device__ float g_qkv[(size_t)Bc * Sc * TD3];        // [B*S, 3072]
__device__ float g_vals[(size_t)Bc * Sc * Dc];        // [B,H,S,hd] contiguous == [B*S, D] reinterpret
__device__ float g_attn_fb[(size_t)Bc * Hc * Sc * Sc]; // fallback if attention not in d_out

// ---------------------------------------------------------------------------
// Generic C = A @ B^T + bias   (A: [M,K] row-major, Bm: [N,K] row-major)
// 128x128 tile, BK=8, 256 threads, 8x8 per-thread microtile
// ---------------------------------------------------------------------------
__global__ __launch_bounds__(256) void gemm_nt_bias(
    const float* __restrict__ A, const float* __restrict__ Bm,
    const float* __restrict__ bias, float* __restrict__ C,
    int M, int N, int K)
{
    __shared__ float As[8][128];
    __shared__ float Bs[8][128];

    const int bm = blockIdx.y * 128;
    const int bn = blockIdx.x * 128;
    const int tid = threadIdx.x;
    const int tx = tid & 15;
    const int ty = tid >> 4;
    const int lrow = tid >> 1;          // 0..127
    const int lcol = (tid & 1) * 4;     // 0 or 4

    float acc[8][8];
#pragma unroll
    for (int i = 0; i < 8; i++)
#pragma unroll
        for (int j = 0; j < 8; j++) acc[i][j] = 0.f;

    const float* aptr = A + (size_t)(bm + lrow) * K + lcol;
    const float* bptr = Bm + (size_t)(bn + lrow) * K + lcol;

    for (int k0 = 0; k0 < K; k0 += 8) {
        float4 av = *(const float4*)(aptr + k0);
        float4 bv = *(const float4*)(bptr + k0);
        As[lcol + 0][lrow] = av.x; As[lcol + 1][lrow] = av.y;
        As[lcol + 2][lrow] = av.z; As[lcol + 3][lrow] = av.w;
        Bs[lcol + 0][lrow] = bv.x; Bs[lcol + 1][lrow] = bv.y;
        Bs[lcol + 2][lrow] = bv.z; Bs[lcol + 3][lrow] = bv.w;
        __syncthreads();
#pragma unroll
        for (int kk = 0; kk < 8; kk++) {
            float a[8], b[8];
#pragma unroll
            for (int i = 0; i < 8; i++) a[i] = As[kk][ty * 8 + i];
#pragma unroll
            for (int j = 0; j < 8; j++) b[j] = Bs[kk][tx * 8 + j];
#pragma unroll
            for (int i = 0; i < 8; i++)
#pragma unroll
                for (int j = 0; j < 8; j++)
                    acc[i][j] = fmaf(a[i], b[j], acc[i][j]);
        }
        __syncthreads();
    }

#pragma unroll
    for (int i = 0; i < 8; i++) {
        const int m = bm + ty * 8 + i;
#pragma unroll
        for (int j = 0; j < 8; j++) {
            const int n = bn + tx * 8 + j;
            C[(size_t)m * N + n] = acc[i][j] + bias[n];
        }
    }
}

// ---------------------------------------------------------------------------
// Attention scores: for z=(b,h), scores[q,k] = dot(Q[q], K[k]) / 8
// Q row = qkv[b*S+q][h*192 + 0..63], K row = qkv[b*S+k][h*192 + 64..127]
// 128x128 tile, BK=8 (K=64)
// ---------------------------------------------------------------------------
__global__ __launch_bounds__(256) void attn_scores(
    const float* __restrict__ qkv, float* __restrict__ attn)
{
    __shared__ float As[8][128];
    __shared__ float Bs[8][128];

    const int z = blockIdx.z;
    const int b = z >> 4;
    const int h = z & 15;
    const float* qbase = qkv + (size_t)b * Sc * TD3 + h * 192;
    const float* kbase = qbase + 64;
    float* cbase = attn + (size_t)z * Sc * Sc;

    const int bm = blockIdx.y * 128;
    const int bn = blockIdx.x * 128;
    const int tid = threadIdx.x;
    const int tx = tid & 15;
    const int ty = tid >> 4;
    const int lrow = tid >> 1;
    const int lcol = (tid & 1) * 4;

    float acc[8][8];
#pragma unroll
    for (int i = 0; i < 8; i++)
#pragma unroll
        for (int j = 0; j < 8; j++) acc[i][j] = 0.f;

    const float* aptr = qbase + (size_t)(bm + lrow) * TD3 + lcol;
    const float* bptr = kbase + (size_t)(bn + lrow) * TD3 + lcol;

    for (int k0 = 0; k0 < HDc; k0 += 8) {
        float4 av = *(const float4*)(aptr + k0);
        float4 bv = *(const float4*)(bptr + k0);
        As[lcol + 0][lrow] = av.x; As[lcol + 1][lrow] = av.y;
        As[lcol + 2][lrow] = av.z; As[lcol + 3][lrow] = av.w;
        Bs[lcol + 0][lrow] = bv.x; Bs[lcol + 1][lrow] = bv.y;
        Bs[lcol + 2][lrow] = bv.z; Bs[lcol + 3][lrow] = bv.w;
        __syncthreads();
#pragma unroll
        for (int kk = 0; kk < 8; kk++) {
            float a[8], bb[8];
#pragma unroll
            for (int i = 0; i < 8; i++) a[i] = As[kk][ty * 8 + i];
#pragma unroll
            for (int j = 0; j < 8; j++) bb[j] = Bs[kk][tx * 8 + j];
#pragma unroll
            for (int i = 0; i < 8; i++)
#pragma unroll
                for (int j = 0; j < 8; j++)
                    acc[i][j] = fmaf(a[i], bb[j], acc[i][j]);
        }
        __syncthreads();
    }

#pragma unroll
    for (int i = 0; i < 8; i++) {
        const int m = bm + ty * 8 + i;
#pragma unroll
        for (int j = 0; j < 8; j++) {
            const int n = bn + tx * 8 + j;
            cbase[(size_t)m * Sc + n] = acc[i][j] * 0.125f;
        }
    }
}

// ---------------------------------------------------------------------------
// Row softmax in-place: one block per row of 2048
// ---------------------------------------------------------------------------
__global__ __launch_bounds__(256) void row_softmax(float* __restrict__ attn)
{
    __shared__ float buf[Sc];
    __shared__ float red[256];
    const int t = threadIdx.x;
    float* row = attn + (size_t)blockIdx.x * Sc;

    float m = -1e30f;
    for (int i = t; i < Sc; i += 256) {
        float v = row[i];
        buf[i] = v;
        m = fmaxf(m, v);
    }
    red[t] = m;
    __syncthreads();
    for (int s = 128; s > 0; s >>= 1) {
        if (t < s) red[t] = fmaxf(red[t], red[t + s]);
        __syncthreads();
    }
    const float rmax = red[0];
    __syncthreads();

    float ssum = 0.f;
    for (int i = t; i < Sc; i += 256) {
        float e = __expf(buf[i] - rmax);
        buf[i] = e;
        ssum += e;
    }
    red[t] = ssum;
    __syncthreads();
    for (int s = 128; s > 0; s >>= 1) {
        if (t < s) red[t] += red[t + s];
        __syncthreads();
    }
    const float inv = 1.f / red[0];
    for (int i = t; i < Sc; i += 256)
        row[i] = buf[i] * inv;
}

// ---------------------------------------------------------------------------
// PV: vals[b,h,q,d] = sum_k attn[z][q,k] * V[b*S+k][h*192+128+d]
// 64x64 tile (N=64), BK=16, 256 threads, 4x4 microtile
// ---------------------------------------------------------------------------
__global__ __launch_bounds__(256) void attn_pv(
    const float* __restrict__ attn, const float* __restrict__ qkv,
    float* __restrict__ vals)
{
    __shared__ float As[16][64];
    __shared__ float Bs[16][64];

    const int z = blockIdx.z;
    const int b = z >> 4;
    const int h = z & 15;
    const float* arow = attn + (size_t)z * Sc * Sc;
    const float* vbase = qkv + (size_t)b * Sc * TD3 + h * 192 + 128;
    float* obase = vals + (size_t)z * Sc * HDc;

    const int bm = blockIdx.y * 64;
    const int tid = threadIdx.x;
    const int tx = tid & 15;
    const int ty = tid >> 4;

    const int a_r = tid >> 2;          // 0..63
    const int a_c = (tid & 3) * 4;     // 0..12
    const int b_k = tid >> 4;          // 0..15
    const int b_n = (tid & 15) * 4;    // 0..60

    float acc[4][4];
#pragma unroll
    for (int i = 0; i < 4; i++)
#pragma unroll
        for (int j = 0; j < 4; j++) acc[i][j] = 0.f;

    for (int k0 = 0; k0 < Sc; k0 += 16) {
        float4 av = *(const float4*)(arow + (size_t)(bm + a_r) * Sc + k0 + a_c);
        As[a_c + 0][a_r] = av.x; As[a_c + 1][a_r] = av.y;
        As[a_c + 2][a_r] = av.z; As[a_c + 3][a_r] = av.w;
        float4 bv = *(const float4*)(vbase + (size_t)(k0 + b_k) * TD3 + b_n);
        *(float4*)&Bs[b_k][b_n] = bv;
        __syncthreads();
#pragma unroll
        for (int kk = 0; kk < 16; kk++) {
            float a[4], bb[4];
#pragma unroll
            for (int i = 0; i < 4; i++) a[i] = As[kk][ty * 4 + i];
#pragma unroll
            for (int j = 0; j < 4; j++) bb[j] = Bs[kk][tx * 4 + j];
#pragma unroll
            for (int i = 0; i < 4; i++)
#pragma unroll
                for (int j = 0; j < 4; j++)
                    acc[i][j] = fmaf(a[i], bb[j], acc[i][j]);
        }
        __syncthreads();
    }

#pragma unroll
    for (int i = 0; i < 4; i++) {
        const int m = bm + ty * 4 + i;
#pragma unroll
        for (int j = 0; j < 4; j++)
            obase[(size_t)m * HDc + tx * 4 + j] = acc[i][j];
    }
}

// ---------------------------------------------------------------------------
extern "C" void kernel_launch(void* const* d_in, const int* in_sizes, int n_in,
                              void* d_out, int out_size)
{
    const float* x     = (const float*)d_in[0];
    const float* w_qkv = (const float*)d_in[1];
    const float* b_qkv = (const float*)d_in[2];
    const float* w_out = (const float*)d_in[3];
    const float* b_out = (const float*)d_in[4];
    float* out = (float*)d_out;

    const size_t BSD  = (size_t)Bc * Sc * Dc;              // 8,388,608
    const size_t BHSS = (size_t)Bc * Hc * Sc * Sc;         // 268,435,456

    float *qkv, *vals, *attn_fb;
    cudaGetSymbolAddress((void**)&qkv,     g_qkv);
    cudaGetSymbolAddress((void**)&vals,    g_vals);
    cudaGetSymbolAddress((void**)&attn_fb, g_attn_fb);

    float* attn = ((size_t)out_size >= BSD + BHSS) ? (out + BSD) : attn_fb;

    // 1) fused QKV projection: [8192,3072] = x @ w_qkv^T + b_qkv
    {
        dim3 grid(TD3 / 128, Mrows / 128);
        gemm_nt_bias<<<grid, 256>>>(x, w_qkv, b_qkv, qkv, Mrows, TD3, Dc);
    }
    // 2) attention scores (scaled)
    {
        dim3 grid(Sc / 128, Sc / 128, Bc * Hc);
        attn_scores<<<grid, 256>>>(qkv, attn);
    }
    // 3) softmax rows in place
    {
        row_softmax<<<Bc * Hc * Sc, 256>>>(attn);
    }
    // 4) PV
    {
        dim3 grid(1, Sc / 64, Bc * Hc);
        attn_pv<<<grid, 256>>>(attn, qkv, vals);
    }
    // 5) output projection: out = vals(reinterp [8192,1024]) @ w_out^T + b_out
    {
        dim3 grid(Dc / 128, Mrows / 128);
        gemm_nt_bias<<<grid, 256>>>(vals, w_out, b_out, out, Mrows, Dc, Dc);
    }
}

// round 4
// speedup vs baseline: 2.5846x; 2.5846x over previous
#include <cuda_runtime.h>
#include <cuda_bf16.h>
#include <cstdint>

// Problem constants
constexpr int Bc  = 4;
constexpr int Sc  = 2048;
constexpr int Dc  = 1024;
constexpr int Hc  = 16;
constexpr int HDc = 64;
constexpr int TD3 = 3 * Dc;          // 3072
constexpr int Mrows = Bc * Sc;       // 8192

// Scratch (device globals; no allocation in kernel_launch)
__device__ float g_qkv[(size_t)Mrows * TD3];
__device__ float g_vals[(size_t)Mrows * Dc];
__device__ float g_attn_fb[(size_t)Bc * Hc * Sc * Sc];

// ---------------------------------------------------------------------------
// helpers
// ---------------------------------------------------------------------------
__device__ __forceinline__ uint32_t smem_u32(const void* p) {
    uint32_t a;
    asm("{ .reg .u64 t; cvta.to.shared.u64 t, %1; cvt.u32.u64 %0, t; }"
        : "=r"(a) : "l"(p));
    return a;
}
__device__ __forceinline__ uint32_t sw64(uint32_t o)  { return o ^ ((o >> 3) & 0x30); }
__device__ __forceinline__ uint32_t sw128(uint32_t o) { return o ^ ((o >> 3) & 0x70); }

__device__ __forceinline__ void ldsm4(uint32_t a, uint32_t r[4]) {
    asm volatile("ldmatrix.sync.aligned.m8n8.x4.shared.b16 {%0,%1,%2,%3}, [%4];"
                 : "=r"(r[0]), "=r"(r[1]), "=r"(r[2]), "=r"(r[3]) : "r"(a));
}
__device__ __forceinline__ void ldsm4t(uint32_t a, uint32_t r[4]) {
    asm volatile("ldmatrix.sync.aligned.m8n8.x4.trans.shared.b16 {%0,%1,%2,%3}, [%4];"
                 : "=r"(r[0]), "=r"(r[1]), "=r"(r[2]), "=r"(r[3]) : "r"(a));
}
__device__ __forceinline__ void mma16816(float d[4], const uint32_t a[4], const uint32_t b[2]) {
    asm volatile(
        "mma.sync.aligned.m16n8k16.row.col.f32.bf16.bf16.f32 "
        "{%0,%1,%2,%3}, {%4,%5,%6,%7}, {%8,%9}, {%0,%1,%2,%3};"
        : "+f"(d[0]), "+f"(d[1]), "+f"(d[2]), "+f"(d[3])
        : "r"(a[0]), "r"(a[1]), "r"(a[2]), "r"(a[3]), "r"(b[0]), "r"(b[1]));
}

// ---------------------------------------------------------------------------
// loaders: fp32 gmem -> regs -> (hi,lo) bf16 swizzled SMEM
// ---------------------------------------------------------------------------
// 128 rows x 32 cols tile: each thread 1 half-row (16 floats)
__device__ __forceinline__ void ldg16(const float* __restrict__ src, int ld, int tid, float4 r[4]) {
    const float4* p = reinterpret_cast<const float4*>(src + (size_t)(tid >> 1) * ld + (tid & 1) * 16);
#pragma unroll
    for (int i = 0; i < 4; i++) r[i] = p[i];
}
__device__ __forceinline__ void cvt_sts(uint8_t* sm, uint32_t hi, uint32_t lo,
                                        uint32_t swoff, float4 v) {
    __nv_bfloat162 h01 = __floats2bfloat162_rn(v.x, v.y);
    __nv_bfloat162 h23 = __floats2bfloat162_rn(v.z, v.w);
    float r0 = v.x - __low2float(h01);
    float r1 = v.y - __high2float(h01);
    float r2 = v.z - __low2float(h23);
    float r3 = v.w - __high2float(h23);
    __nv_bfloat162 l01 = __floats2bfloat162_rn(r0, r1);
    __nv_bfloat162 l23 = __floats2bfloat162_rn(r2, r3);
    uint2 hw, lw;
    hw.x = *reinterpret_cast<uint32_t*>(&h01); hw.y = *reinterpret_cast<uint32_t*>(&h23);
    lw.x = *reinterpret_cast<uint32_t*>(&l01); lw.y = *reinterpret_cast<uint32_t*>(&l23);
    *reinterpret_cast<uint2*>(sm + hi + swoff) = hw;
    *reinterpret_cast<uint2*>(sm + lo + swoff) = lw;
}
// store 128x32 tile, 64B rows, SW64
__device__ __forceinline__ void sts16(uint8_t* sm, uint32_t hi, uint32_t lo, int tid, const float4 r[4]) {
    const uint32_t base = (uint32_t)(tid >> 1) * 64 + (uint32_t)(tid & 1) * 32;
#pragma unroll
    for (int i = 0; i < 4; i++) cvt_sts(sm, hi, lo, sw64(base + i * 8), r[i]);
}
// V chunk: 32 k-rows x 64 d-cols natural layout, 128B rows, SW128
__device__ __forceinline__ void ldgV(const float* __restrict__ src, int tid, float4 r[2]) {
    const float4* p = reinterpret_cast<const float4*>(src + (size_t)(tid >> 3) * TD3 + (tid & 7) * 8);
    r[0] = p[0]; r[1] = p[1];
}
__device__ __forceinline__ void stsV(uint8_t* sm, uint32_t hi, uint32_t lo, int tid, const float4 r[2]) {
    const uint32_t base = (uint32_t)(tid >> 3) * 128 + (uint32_t)(tid & 7) * 16;
    cvt_sts(sm, hi, lo, sw128(base), r[0]);
    cvt_sts(sm, hi, lo, sw128(base + 8), r[1]);
}

// ---------------------------------------------------------------------------
// compute cores (one BK=32 chunk)
// ---------------------------------------------------------------------------
// generic: warp tile 32x64 over 128x128 block; A,B both [rows][32] SW64
__device__ __forceinline__ void compute64(uint32_t sb, int wm, int wn, int lane,
                                          float acc[2][8][4]) {
    const uint32_t Ah = sb, Al = sb + 8192, Bh = sb + 16384, Bl = sb + 24576;
    const int arow = ((lane >> 3) & 1) * 8 + (lane & 7);
    const int brow = ((lane >> 4) & 1) * 8 + (lane & 7);
#pragma unroll
    for (int ks = 0; ks < 2; ks++) {
        const uint32_t akb = ks * 32 + ((lane >> 4) & 1) * 16;
        const uint32_t bkb = ks * 32 + ((lane >> 3) & 1) * 16;
        uint32_t ah[2][4], al[2][4];
#pragma unroll
        for (int mt = 0; mt < 2; mt++) {
            const uint32_t off = sw64((uint32_t)(wm + mt * 16 + arow) * 64 + akb);
            ldsm4(Ah + off, ah[mt]);
            ldsm4(Al + off, al[mt]);
        }
        uint32_t bh[8][2], bl[8][2];
#pragma unroll
        for (int p = 0; p < 4; p++) {
            const uint32_t off = sw64((uint32_t)(wn + p * 16 + brow) * 64 + bkb);
            uint32_t t[4];
            ldsm4(Bh + off, t);
            bh[2*p][0] = t[0]; bh[2*p][1] = t[1]; bh[2*p+1][0] = t[2]; bh[2*p+1][1] = t[3];
            ldsm4(Bl + off, t);
            bl[2*p][0] = t[0]; bl[2*p][1] = t[1]; bl[2*p+1][0] = t[2]; bl[2*p+1][1] = t[3];
        }
#pragma unroll
        for (int nt = 0; nt < 8; nt++) {
#pragma unroll
            for (int mt = 0; mt < 2; mt++) {
                mma16816(acc[mt][nt], ah[mt], bh[nt]);
                mma16816(acc[mt][nt], ah[mt], bl[nt]);
                mma16816(acc[mt][nt], al[mt], bh[nt]);
            }
        }
    }
}

// PV: warp tile 32x32 over 128x64 block; A [128][32] SW64, V [32][64] SW128 (trans load)
__device__ __forceinline__ void computePV(uint32_t sb, int wm, int wn, int lane,
                                          float acc[2][4][4]) {
    const uint32_t Ah = sb, Al = sb + 8192, Vh = sb + 16384, Vl = sb + 20480;
    const int arow = ((lane >> 3) & 1) * 8 + (lane & 7);
    const int krw  = ((lane >> 3) & 1) * 8 + (lane & 7);
    const int dof  = ((lane >> 4) & 1) * 8;
#pragma unroll
    for (int ks = 0; ks < 2; ks++) {
        const uint32_t akb = ks * 32 + ((lane >> 4) & 1) * 16;
        uint32_t ah[2][4], al[2][4];
#pragma unroll
        for (int mt = 0; mt < 2; mt++) {
            const uint32_t off = sw64((uint32_t)(wm + mt * 16 + arow) * 64 + akb);
            ldsm4(Ah + off, ah[mt]);
            ldsm4(Al + off, al[mt]);
        }
        uint32_t vh[4][2], vl[4][2];
#pragma unroll
        for (int p = 0; p < 2; p++) {
            const uint32_t off = sw128((uint32_t)(ks * 16 + krw) * 128 +
                                       (uint32_t)(wn + p * 16 + dof) * 2);
            uint32_t t[4];
            ldsm4t(Vh + off, t);
            vh[2*p][0] = t[0]; vh[2*p][1] = t[1]; vh[2*p+1][0] = t[2]; vh[2*p+1][1] = t[3];
            ldsm4t(Vl + off, t);
            vl[2*p][0] = t[0]; vl[2*p][1] = t[1]; vl[2*p+1][0] = t[2]; vl[2*p+1][1] = t[3];
        }
#pragma unroll
        for (int nt = 0; nt < 4; nt++) {
#pragma unroll
            for (int mt = 0; mt < 2; mt++) {
                mma16816(acc[mt][nt], ah[mt], vh[nt]);
                mma16816(acc[mt][nt], ah[mt], vl[nt]);
                mma16816(acc[mt][nt], al[mt], vh[nt]);
            }
        }
    }
}

// ---------------------------------------------------------------------------
// Kernel: C[128x128 tiles] = (A @ B^T) * scale + bias; z-batched via strides
// smem: 2 buffers x 32KB (Ah,Al,Bh,Bl each 8KB)
// ---------------------------------------------------------------------------
__global__ __launch_bounds__(256, 1) void gemm_mma(
    const float* __restrict__ A, int lda, long sAz,
    const float* __restrict__ B, int ldb, long sBz,
    float* __restrict__ C, long sCz, int ldc, int K,
    const float* __restrict__ bias, float scale)
{
    extern __shared__ uint8_t sm[];
    const uint32_t sb0 = smem_u32(sm);
    const int tid = threadIdx.x, lane = tid & 31, w = tid >> 5;
    const int wm = (w & 3) * 32, wn = (w >> 2) * 64;

    A += (size_t)blockIdx.z * sAz + (size_t)(blockIdx.y * 128) * lda;
    B += (size_t)blockIdx.z * sBz + (size_t)(blockIdx.x * 128) * ldb;
    C += (size_t)blockIdx.z * sCz;

    float acc[2][8][4] = {};
    float4 ra[4], rb[4];
    ldg16(A, lda, tid, ra);
    ldg16(B, ldb, tid, rb);

    const int NC = K >> 5;
    for (int c = 0; c < NC; c++) {
        const uint32_t buf = (uint32_t)(c & 1) * 32768;
        sts16(sm, buf, buf + 8192, tid, ra);
        sts16(sm, buf + 16384, buf + 24576, tid, rb);
        __syncthreads();
        if (c + 1 < NC) {
            ldg16(A + (c + 1) * 32, lda, tid, ra);
            ldg16(B + (c + 1) * 32, ldb, tid, rb);
        }
        compute64(sb0 + buf, wm, wn, lane, acc);
    }

    const int gr = blockIdx.y * 128 + wm + (lane >> 2);
    const int gc = blockIdx.x * 128 + wn + (lane & 3) * 2;
#pragma unroll
    for (int mt = 0; mt < 2; mt++) {
        const int r0 = gr + mt * 16;
#pragma unroll
        for (int nt = 0; nt < 8; nt++) {
            const int cc = gc + nt * 8;
            float b0 = 0.f, b1 = 0.f;
            if (bias) { b0 = __ldg(bias + cc); b1 = __ldg(bias + cc + 1); }
            float2 v0 = {acc[mt][nt][0] * scale + b0, acc[mt][nt][1] * scale + b1};
            float2 v1 = {acc[mt][nt][2] * scale + b0, acc[mt][nt][3] * scale + b1};
            *reinterpret_cast<float2*>(C + (size_t)r0 * ldc + cc) = v0;
            *reinterpret_cast<float2*>(C + (size_t)(r0 + 8) * ldc + cc) = v1;
        }
    }
}

// ---------------------------------------------------------------------------
// Kernel: PV  vals[z][q][d] = sum_k P[z][q,k] * V[k,d]
// grid (16 q-tiles, 64 z); smem 2 x 24KB
// ---------------------------------------------------------------------------
__global__ __launch_bounds__(256, 1) void pv_mma(
    const float* __restrict__ attn, const float* __restrict__ qkv,
    float* __restrict__ vals)
{
    extern __shared__ uint8_t sm[];
    const uint32_t sb0 = smem_u32(sm);
    const int tid = threadIdx.x, lane = tid & 31, w = tid >> 5;
    const int wm = (w & 3) * 32, wn = (w >> 2) * 32;

    const int z = blockIdx.y, b = z >> 4, h = z & 15;
    const float* A = attn + (size_t)z * Sc * Sc + (size_t)(blockIdx.x * 128) * Sc;
    const float* V = qkv + (size_t)b * Sc * TD3 + h * 192 + 128;

    float acc[2][4][4] = {};
    float4 ra[4], rv[2];
    ldg16(A, Sc, tid, ra);
    ldgV(V, tid, rv);

    for (int c = 0; c < 64; c++) {
        const uint32_t buf = (uint32_t)(c & 1) * 24576;
        sts16(sm, buf, buf + 8192, tid, ra);
        stsV(sm, buf + 16384, buf + 20480, tid, rv);
        __syncthreads();
        if (c < 63) {
            ldg16(A + (c + 1) * 32, Sc, tid, ra);
            ldgV(V + (size_t)(c + 1) * 32 * TD3, tid, rv);
        }
        computePV(sb0 + buf, wm, wn, lane, acc);
    }

    float* Co = vals + (size_t)z * Sc * HDc + (size_t)(blockIdx.x * 128) * HDc;
    const int r0b = wm + (lane >> 2);
    const int ccb = wn + (lane & 3) * 2;
#pragma unroll
    for (int mt = 0; mt < 2; mt++) {
        const int r0 = r0b + mt * 16;
#pragma unroll
        for (int nt = 0; nt < 4; nt++) {
            const int cc = ccb + nt * 8;
            float2 v0 = {acc[mt][nt][0], acc[mt][nt][1]};
            float2 v1 = {acc[mt][nt][2], acc[mt][nt][3]};
            *reinterpret_cast<float2*>(Co + (size_t)r0 * HDc + cc) = v0;
            *reinterpret_cast<float2*>(Co + (size_t)(r0 + 8) * HDc + cc) = v1;
        }
    }
}

// ---------------------------------------------------------------------------
// Row softmax in-place: register-resident, one block of 256 per row of 2048
// ---------------------------------------------------------------------------
__global__ __launch_bounds__(256) void row_softmax(float* __restrict__ attn)
{
    __shared__ float red[8];
    const int t = threadIdx.x;
    float4* row = reinterpret_cast<float4*>(attn + (size_t)blockIdx.x * Sc);
    float4 v0 = row[t];
    float4 v1 = row[t + 256];

    float m = fmaxf(fmaxf(fmaxf(v0.x, v0.y), fmaxf(v0.z, v0.w)),
                    fmaxf(fmaxf(v1.x, v1.y), fmaxf(v1.z, v1.w)));
#pragma unroll
    for (int o = 16; o; o >>= 1) m = fmaxf(m, __shfl_xor_sync(0xFFFFFFFFu, m, o));
    if ((t & 31) == 0) red[t >> 5] = m;
    __syncthreads();
    m = red[0];
#pragma unroll
    for (int i = 1; i < 8; i++) m = fmaxf(m, red[i]);
    __syncthreads();

    v0.x = __expf(v0.x - m); v0.y = __expf(v0.y - m);
    v0.z = __expf(v0.z - m); v0.w = __expf(v0.w - m);
    v1.x = __expf(v1.x - m); v1.y = __expf(v1.y - m);
    v1.z = __expf(v1.z - m); v1.w = __expf(v1.w - m);
    float s = (v0.x + v0.y) + (v0.z + v0.w) + (v1.x + v1.y) + (v1.z + v1.w);
#pragma unroll
    for (int o = 16; o; o >>= 1) s += __shfl_xor_sync(0xFFFFFFFFu, s, o);
    if ((t & 31) == 0) red[t >> 5] = s;
    __syncthreads();
    s = red[0];
#pragma unroll
    for (int i = 1; i < 8; i++) s += red[i];
    const float inv = 1.f / s;

    v0.x *= inv; v0.y *= inv; v0.z *= inv; v0.w *= inv;
    v1.x *= inv; v1.y *= inv; v1.z *= inv; v1.w *= inv;
    row[t] = v0;
    row[t + 256] = v1;
}

// ---------------------------------------------------------------------------
extern "C" void kernel_launch(void* const* d_in, const int* in_sizes, int n_in,
                              void* d_out, int out_size)
{
    const float* x     = (const float*)d_in[0];
    const float* w_qkv = (const float*)d_in[1];
    const float* b_qkv = (const float*)d_in[2];
    const float* w_out = (const float*)d_in[3];
    const float* b_out = (const float*)d_in[4];
    float* out = (float*)d_out;

    const size_t BSD  = (size_t)Bc * Sc * Dc;
    const size_t BHSS = (size_t)Bc * Hc * Sc * Sc;

    float *qkv, *vals, *attn_fb;
    cudaGetSymbolAddress((void**)&qkv,     g_qkv);
    cudaGetSymbolAddress((void**)&vals,    g_vals);
    cudaGetSymbolAddress((void**)&attn_fb, g_attn_fb);

    float* attn = ((size_t)out_size >= BSD + BHSS) ? (out + BSD) : attn_fb;

    cudaFuncSetAttribute(gemm_mma, cudaFuncAttributeMaxDynamicSharedMemorySize, 65536);
    cudaFuncSetAttribute(pv_mma,   cudaFuncAttributeMaxDynamicSharedMemorySize, 49152);

    // 1) fused QKV projection: [8192,3072] = x @ w_qkv^T + b_qkv
    gemm_mma<<<dim3(TD3 / 128, Mrows / 128, 1), 256, 65536>>>(
        x, Dc, 0, w_qkv, Dc, 0, qkv, 0, TD3, Dc, b_qkv, 1.f);

    // 2) attention scores: per batch, z = head (stride 192 inside qkv rows)
    for (int b = 0; b < Bc; b++) {
        const float* base = qkv + (size_t)b * Sc * TD3;
        gemm_mma<<<dim3(Sc / 128, Sc / 128, Hc), 256, 65536>>>(
            base, TD3, 192, base + 64, TD3, 192,
            attn + (size_t)b * Hc * Sc * Sc, (long)Sc * Sc, Sc, HDc,
            nullptr, 0.125f);
    }

    // 3) softmax rows in place
    row_softmax<<<Bc * Hc * Sc, 256>>>(attn);

    // 4) PV
    pv_mma<<<dim3(Sc / 128, Bc * Hc), 256, 49152>>>(attn, qkv, vals);

    // 5) output projection: out = vals @ w_out^T + b_out
    gemm_mma<<<dim3(Dc / 128, Mrows / 128, 1), 256, 65536>>>(
        vals, Dc, 0, w_out, Dc, 0, out, 0, Dc, Dc, b_out, 1.f);
}